// round 14
// baseline (speedup 1.0000x reference)
#include <cuda_runtime.h>

#define N_NODES 50000
#define N_EDGES 640000
#define IN_DIM 128
#define HID 128
#define G_OUT 128
#define AX_IN 64
#define AX_OUT 64
#define OUT_CH 8
#define N_GRAPHS 512

#define SCAN_BLK 49               // ceil(50000/1024)
#define GEMM_TILES ((N_NODES + 127) / 128)   // 391

// ---------------- scratch (device globals; no allocation) ----------------
__device__ int   g_deg_i[N_NODES];
__device__ int   g_rowptr[N_NODES];
__device__ int   g_cursor[N_NODES];
__device__ int   g_csr_src[N_EDGES];
__device__ int   g_bsum[SCAN_BLK];
__device__ int   g_boff[SCAN_BLK];
__device__ float g_dinv[N_NODES];
__device__ float g_H[N_NODES * HID];
__device__ float g_ACC[N_NODES * HID];
__device__ float g_sums[N_GRAPHS * HID];
__device__ float g_cnts[N_GRAPHS];

// ---------------- init ----------------
__global__ void init_kernel() {
    int i = blockIdx.x * blockDim.x + threadIdx.x;
    if (i < N_NODES) g_deg_i[i] = 0;
    if (i < N_GRAPHS * HID) g_sums[i] = 0.0f;
    if (i < N_GRAPHS) g_cnts[i] = 0.0f;
}

__global__ void count_deg_kernel(const int* __restrict__ ei) {
    int e = blockIdx.x * blockDim.x + threadIdx.x;
    if (e >= N_EDGES) return;
    atomicAdd(&g_deg_i[ei[N_EDGES + e]], 1);   // REDG int
}

// ---------------- scan phase 1: per-chunk sums ----------------
__global__ void bsum_kernel() {
    __shared__ int tsum[256];
    int b = blockIdx.x, t = threadIdx.x;
    int base = b * 1024 + t * 4;
    int s = 0;
#pragma unroll
    for (int j = 0; j < 4; j++) {
        int idx = base + j;
        if (idx < N_NODES) s += g_deg_i[idx];
    }
    tsum[t] = s;
    __syncthreads();
    for (int off = 128; off > 0; off >>= 1) {
        if (t < off) tsum[t] += tsum[t + off];
        __syncthreads();
    }
    if (t == 0) g_bsum[b] = tsum[0];
}

// ---------------- scan phase 2: exclusive scan of chunk sums --------------
__global__ void bscan_kernel() {
    __shared__ int v[64];
    int t = threadIdx.x;
    v[t] = (t < SCAN_BLK) ? g_bsum[t] : 0;
    __syncthreads();
    for (int off = 1; off < 64; off <<= 1) {
        int x = 0;
        if (t >= off) x = v[t - off];
        __syncthreads();
        if (t >= off) v[t] += x;
        __syncthreads();
    }
    if (t < SCAN_BLK) g_boff[t] = (t > 0) ? v[t - 1] : 0;
}

// ---------------- scan phase 3: rowptr/cursor + dinv ----------------
__global__ void rowptr_kernel() {
    __shared__ int tsum[256];
    int b = blockIdx.x, t = threadIdx.x;
    int base = b * 1024 + t * 4;
    int d[4];
    int s = 0;
#pragma unroll
    for (int j = 0; j < 4; j++) {
        int idx = base + j;
        d[j] = (idx < N_NODES) ? g_deg_i[idx] : 0;
        s += d[j];
    }
    tsum[t] = s;
    __syncthreads();
    for (int off = 1; off < 256; off <<= 1) {
        int x = 0;
        if (t >= off) x = tsum[t - off];
        __syncthreads();
        if (t >= off) tsum[t] += x;
        __syncthreads();
    }
    int run = g_boff[b] + ((t > 0) ? tsum[t - 1] : 0);
#pragma unroll
    for (int j = 0; j < 4; j++) {
        int idx = base + j;
        if (idx < N_NODES) {
            g_rowptr[idx] = run;
            g_cursor[idx] = run;
            run += d[j];
            g_dinv[idx] = rsqrtf(1.0f + (float)d[j]);   // self loop adds 1
        }
    }
}

__global__ void fill_kernel(const int* __restrict__ ei) {
    int e = blockIdx.x * blockDim.x + threadIdx.x;
    if (e >= N_EDGES) return;
    int s = ei[e];
    int d = ei[N_EDGES + e];
    int p = atomicAdd(&g_cursor[d], 1);
    g_csr_src[p] = s;
}

// ---------------- dense GEMM: H[N,128] = f(X)[N,128] @ W[128,128] ----------
// 128x128 tile per block, 256 threads, 8x8 micro-tile, float4 LDS on both
// operands (4 LDS.128 per 64 FMA). Xs staged transposed: Xs[kk][row],
// pitch 132 floats (16B-aligned rows; x-reads are warp-broadcast).
template <bool RELU>
__global__ void __launch_bounds__(256) gemm_kernel(
    const float* __restrict__ X,
    const float* __restrict__ W,
    float* __restrict__ H) {
    __shared__ float Xs[16][132];   // [kk][row]
    __shared__ float Ws[16][128];   // [kk][col]
    int tid = threadIdx.x;          // 0..255
    int tr = tid >> 4;              // row group: rows tr*8 .. tr*8+7
    int tc = tid & 15;              // col group: cols tc*8 .. tc*8+7
    int row0 = blockIdx.x * 128;

    float acc[8][8];
#pragma unroll
    for (int i = 0; i < 8; i++)
#pragma unroll
        for (int j = 0; j < 8; j++) acc[i][j] = 0.0f;

    for (int k0 = 0; k0 < 128; k0 += 16) {
        // stage X tile 128x16 (transposed into Xs[kk][row])
        {
            int r = tid >> 1;               // 0..127
            int kh = (tid & 1) * 8;         // 0 or 8
            int gr = row0 + r;
            float4 v0, v1;
            if (gr < N_NODES) {
                const float* xr = &X[(long)gr * 128 + k0 + kh];
                v0 = *(const float4*)xr;
                v1 = *(const float4*)(xr + 4);
            } else {
                v0 = make_float4(0.f, 0.f, 0.f, 0.f);
                v1 = v0;
            }
            if (RELU) {
                v0.x = fmaxf(v0.x, 0.f); v0.y = fmaxf(v0.y, 0.f);
                v0.z = fmaxf(v0.z, 0.f); v0.w = fmaxf(v0.w, 0.f);
                v1.x = fmaxf(v1.x, 0.f); v1.y = fmaxf(v1.y, 0.f);
                v1.z = fmaxf(v1.z, 0.f); v1.w = fmaxf(v1.w, 0.f);
            }
            Xs[kh + 0][r] = v0.x; Xs[kh + 1][r] = v0.y;
            Xs[kh + 2][r] = v0.z; Xs[kh + 3][r] = v0.w;
            Xs[kh + 4][r] = v1.x; Xs[kh + 5][r] = v1.y;
            Xs[kh + 6][r] = v1.z; Xs[kh + 7][r] = v1.w;
        }
        // stage W tile 16x128 (direct copy, float4)
        {
            int f = tid * 2;                // float4 index, 512 total
            int kk = f >> 5;                // 0..15
            int n4 = (f & 31) * 4;          // float offset 0..124
            const float* wr = &W[(k0 + kk) * 128 + n4];
            *(float4*)&Ws[kk][n4] = *(const float4*)wr;
            *(float4*)&Ws[kk][n4 + 4] = *(const float4*)(wr + 4);
        }
        __syncthreads();
#pragma unroll
        for (int kk = 0; kk < 16; kk++) {
            float xv[8], wv[8];
            *(float4*)&xv[0] = *(const float4*)&Xs[kk][tr * 8];
            *(float4*)&xv[4] = *(const float4*)&Xs[kk][tr * 8 + 4];
            *(float4*)&wv[0] = *(const float4*)&Ws[kk][tc * 8];
            *(float4*)&wv[4] = *(const float4*)&Ws[kk][tc * 8 + 4];
#pragma unroll
            for (int i = 0; i < 8; i++)
#pragma unroll
                for (int j = 0; j < 8; j++)
                    acc[i][j] += xv[i] * wv[j];
        }
        __syncthreads();
    }

#pragma unroll
    for (int i = 0; i < 8; i++) {
        int gr = row0 + tr * 8 + i;
        if (gr < N_NODES) {
            float4 v0 = make_float4(acc[i][0], acc[i][1], acc[i][2], acc[i][3]);
            float4 v1 = make_float4(acc[i][4], acc[i][5], acc[i][6], acc[i][7]);
            float* hr = &H[(long)gr * 128 + tc * 8];
            *(float4*)hr = v0;
            *(float4*)(hr + 4) = v1;
        }
    }
}

// ---------------- gather aggregation (atomic-free) -------------------------
// one warp per dst node; lane owns 4 contiguous floats
// ACC[d] = b + dinv[d]^2 * H[d] + sum_{s in N(d)} dinv[s]*dinv[d] * H[s]
__global__ void gather_kernel(const float* __restrict__ H,
                              const float* __restrict__ b,
                              float* __restrict__ ACC) {
    int warp = (blockIdx.x * blockDim.x + threadIdx.x) >> 5;
    int lane = threadIdx.x & 31;
    if (warp >= N_NODES) return;
    int d = warp;
    float dv = g_dinv[d];
    int start = g_rowptr[d];
    int deg = g_deg_i[d];

    float4 bv = *(const float4*)&b[lane * 4];
    float4 hv = *(const float4*)&H[d * 128 + lane * 4];
    float s2 = dv * dv;
    float a0 = bv.x + s2 * hv.x;
    float a1 = bv.y + s2 * hv.y;
    float a2 = bv.z + s2 * hv.z;
    float a3 = bv.w + s2 * hv.w;

    int k = 0;
    for (; k + 2 <= deg; k += 2) {
        int s0 = g_csr_src[start + k];
        int s1 = g_csr_src[start + k + 1];
        float w0 = dv * g_dinv[s0];
        float w1 = dv * g_dinv[s1];
        float4 h0 = *(const float4*)&H[s0 * 128 + lane * 4];
        float4 h1 = *(const float4*)&H[s1 * 128 + lane * 4];
        a0 += w0 * h0.x + w1 * h1.x;
        a1 += w0 * h0.y + w1 * h1.y;
        a2 += w0 * h0.z + w1 * h1.z;
        a3 += w0 * h0.w + w1 * h1.w;
    }
    if (k < deg) {
        int s0 = g_csr_src[start + k];
        float w0 = dv * g_dinv[s0];
        float4 h0 = *(const float4*)&H[s0 * 128 + lane * 4];
        a0 += w0 * h0.x; a1 += w0 * h0.y; a2 += w0 * h0.z; a3 += w0 * h0.w;
    }
    *(float4*)&ACC[d * 128 + lane * 4] = make_float4(a0, a1, a2, a3);
}

// ---------------- pooling: sums[batch[i]] += relu(ACC[i]); cnts++ ---------
__global__ void pool_kernel(const float* __restrict__ ACC,
                            const int* __restrict__ batch) {
    int idx = blockIdx.x * blockDim.x + threadIdx.x;
    int i = idx >> 5;
    if (i >= N_NODES) return;
    int c = (idx & 31) * 4;
    int g = batch[i];
    float4 v = *(const float4*)&ACC[i * 128 + c];
    float* out = &g_sums[g * 128 + c];
    atomicAdd(out + 0, fmaxf(v.x, 0.0f));
    atomicAdd(out + 1, fmaxf(v.y, 0.0f));
    atomicAdd(out + 2, fmaxf(v.z, 0.0f));
    atomicAdd(out + 3, fmaxf(v.w, 0.0f));
    if ((idx & 31) == 0) atomicAdd(&g_cnts[g], 1.0f);
}

// ---------------- head MLP ----------------
__global__ void head_kernel(const float* __restrict__ ax,
                            const float* __restrict__ l1W, const float* __restrict__ l1b,
                            const float* __restrict__ axW, const float* __restrict__ axb,
                            const float* __restrict__ l2W, const float* __restrict__ l2b,
                            float* __restrict__ out) {
    __shared__ float pooled[128];
    __shared__ float z[192];
    int g = blockIdx.x;
    int t = threadIdx.x;
    float cnt = fmaxf(g_cnts[g], 1.0f);
    pooled[t] = g_sums[g * 128 + t] / cnt;
    __syncthreads();

    float acc = l1b[t];
#pragma unroll 8
    for (int k = 0; k < 128; k++) acc += pooled[k] * l1W[k * 128 + t];
    z[t] = acc;

    if (t < 64) {
        float a = axb[t];
#pragma unroll 8
        for (int k = 0; k < 64; k++) a += ax[g * 64 + k] * axW[k * 64 + t];
        z[128 + t] = a;
    }
    __syncthreads();

    if (t < 8) {
        float o = l2b[t];
#pragma unroll 8
        for (int k = 0; k < 192; k++) o += z[k] * l2W[k * 8 + t];
        out[g * 8 + t] = o;
    }
}

// ---------------- launch --------------------------------------------------
extern "C" void kernel_launch(void* const* d_in, const int* in_sizes, int n_in,
                              void* d_out, int out_size) {
    const float* x = (const float*)d_in[0];
    const int* ei = (const int*)d_in[1];
    const int* batch = (const int*)d_in[2];
    const float* ax = (const float*)d_in[3];
    const float* W1 = (const float*)d_in[4];
    const float* b1 = (const float*)d_in[5];
    const float* W2 = (const float*)d_in[6];
    const float* b2 = (const float*)d_in[7];
    const float* l1W = (const float*)d_in[8];
    const float* l1b = (const float*)d_in[9];
    const float* axW = (const float*)d_in[10];
    const float* axb = (const float*)d_in[11];
    const float* l2W = (const float*)d_in[12];
    const float* l2b = (const float*)d_in[13];
    float* out = (float*)d_out;

    float *dH, *dACC;
    cudaGetSymbolAddress((void**)&dH, g_H);
    cudaGetSymbolAddress((void**)&dACC, g_ACC);

    // ---- CSR build (parallel 3-phase scan) ----
    init_kernel<<<(N_GRAPHS * HID + 255) / 256, 256>>>();
    count_deg_kernel<<<(N_EDGES + 255) / 256, 256>>>(ei);
    bsum_kernel<<<SCAN_BLK, 256>>>();
    bscan_kernel<<<1, 64>>>();
    rowptr_kernel<<<SCAN_BLK, 256>>>();
    fill_kernel<<<(N_EDGES + 255) / 256, 256>>>(ei);

    // ---- layer 1 ----
    gemm_kernel<false><<<GEMM_TILES, 256>>>(x, W1, dH);
    gather_kernel<<<(N_NODES * 32 + 255) / 256, 256>>>(dH, b1, dACC);

    // ---- layer 2 (relu applied on GEMM input load) ----
    gemm_kernel<true><<<GEMM_TILES, 256>>>(dACC, W2, dH);
    gather_kernel<<<(N_NODES * 32 + 255) / 256, 256>>>(dH, b2, dACC);

    // ---- pooling (relu applied here) ----
    pool_kernel<<<(N_NODES * 32 + 255) / 256, 256>>>(dACC, batch);

    // ---- head MLP ----
    head_kernel<<<N_GRAPHS, 128>>>(ax, l1W, l1b, axW, axb, l2W, l2b, out);
}